// round 13
// baseline (speedup 1.0000x reference)
#include <cuda_runtime.h>

// Problem constants (fixed by setup_inputs)
#define NB        64
#define SD        52
#define CELLS     (SD * SD)             // 2704
#define CH        255
#define QCELLS    4                     // cells per warp-iteration
#define NQUADS    (NB * CELLS / QCELLS) // 43264
#define QPI       (CELLS / QCELLS)      // 676 quads per image
#define GRIDP     1036                  // 7 blocks/SM * 148
#define NWARPS    (GRIDP * 4)           // 4144 persistent warps
#define EPSF      1e-6f
#define IOU_T     0.7f
#define SCALE_IDX 2

__device__ __forceinline__ float warp_sum(float v) {
    #pragma unroll
    for (int o = 16; o > 0; o >>= 1) v += __shfl_down_sync(0xffffffffu, v, o);
    return v;
}

// Load the 30 raw box-field values for quad q (8-lane-group broadcast LDGs).
__device__ __forceinline__ void load_fields(
    const float* __restrict__ yhat, const float* __restrict__ ytru,
    int q, int g, float* F)    // F[30]: hx hy hw hh hc (x3) | yx yy yw yh yc (x3)
{
    const int n  = q / QPI;
    const int c0 = (q - n * QPI) * QCELLS;
    const size_t base = ((size_t)n * CELLS + c0 + g) * CH;
    const float* Hb = yhat + base;
    const float* Yb = ytru + base;
    #pragma unroll
    for (int b = 0; b < 3; b++) {
        #pragma unroll
        for (int f = 0; f < 5; f++) {
            F[b * 5 + f]      = __ldg(Hb + b * 85 + f);
            F[15 + b * 5 + f] = __ldg(Yb + b * 85 + f);
        }
    }
}

__global__ __launch_bounds__(128, 7) void yolo_loss_kernel(
    const float* __restrict__ yhat,
    const float* __restrict__ ytru,
    const float* __restrict__ anchors,
    float* __restrict__ out)
{
    const int wl   = threadIdx.x >> 5;
    const int lane = threadIdx.x & 31;
    const int w0   = blockIdx.x * 4 + wl;     // persistent warp id
    const int g    = lane >> 3;               // cell within quad (0..3)
    const int sub  = lane & 7;

    const float invS = 1.0f / (float)SD;

    float aw[3], ah[3];
    #pragma unroll
    for (int b = 0; b < 3; b++) {
        aw[b] = __ldg(anchors + SCALE_IDX * 6 + 2 * b);
        ah[b] = __ldg(anchors + SCALE_IDX * 6 + 2 * b + 1);
    }

    // Prologue: fields of first quad.
    float Fc[30], Fn[30];
    if (w0 < NQUADS) load_fields(yhat, ytru, w0, g, Fn);

    for (int q = w0; q < NQUADS; q += NWARPS) {
        #pragma unroll
        for (int i = 0; i < 30; i++) Fc[i] = Fn[i];

        // ---- Prefetch next quad's fields FIRST: in flight through all of
        // this iteration's compute + class-load stall.
        const int qn = q + NWARPS;
        if (qn < NQUADS) load_fields(yhat, ytru, qn, g, Fn);

        // ---- Decode current quad.
        const int n    = q / QPI;
        const int c0   = (q - n * QPI) * QCELLS;
        const int cellIdx = c0 + g;
        const int gi = cellIdx / SD;
        const int gj = cellIdx - gi * SD;
        const float fj = (float)gj, fi = (float)gi;

        const size_t base = ((size_t)n * CELLS + cellIdx) * CH;
        const float* Hb = yhat + base;
        const float* Yb = ytru + base;

        float hcx[3], hcy[3], hw[3], hh[3], hcf[3];
        float ycx[3], ycy[3], yw[3], yh[3], ycf[3];
        #pragma unroll
        for (int b = 0; b < 3; b++) {
            hcx[b] = (Fc[b * 5 + 0] + fj) * invS;
            hcy[b] = (Fc[b * 5 + 1] + fi) * invS;
            hw[b]  =  Fc[b * 5 + 2];
            hh[b]  =  Fc[b * 5 + 3];
            hcf[b] =  Fc[b * 5 + 4];
            ycx[b] = (Fc[15 + b * 5 + 0] + fj) * invS;
            ycy[b] = (Fc[15 + b * 5 + 1] + fi) * invS;
            yw[b]  =  Fc[15 + b * 5 + 2];
            yh[b]  =  Fc[15 + b * 5 + 3];
            ycf[b] =  Fc[15 + b * 5 + 4];
        }

        // ---- IOU 3x3: per-pb max -> noobj; per-tb argmax -> responsible box.
        int   idx_t[3];
        float best_t[3] = {-1.0f, -1.0f, -1.0f};
        float noobj_acc = 0.0f;
        #pragma unroll
        for (int pb = 0; pb < 3; pb++) {
            float px1 = hcx[pb] - 0.5f * hw[pb], px2 = hcx[pb] + 0.5f * hw[pb];
            float py1 = hcy[pb] - 0.5f * hh[pb], py2 = hcy[pb] + 0.5f * hh[pb];
            float pa  = hw[pb] * hh[pb];
            float m = -1.0f;
            #pragma unroll
            for (int tb = 0; tb < 3; tb++) {
                float wi = fmaxf(fminf(px2, ycx[tb] + 0.5f * yw[tb]) -
                                 fmaxf(px1, ycx[tb] - 0.5f * yw[tb]), 0.0f);
                float hi = fmaxf(fminf(py2, ycy[tb] + 0.5f * yh[tb]) -
                                 fmaxf(py1, ycy[tb] - 0.5f * yh[tb]), 0.0f);
                float inter = wi * hi;
                float uni = pa + yw[tb] * yh[tb] - inter;
                float iou = inter / (uni + EPSF);
                m = fmaxf(m, iou);
                if (iou > best_t[tb]) { best_t[tb] = iou; idx_t[tb] = pb; }
            }
            if (sub == 0 && m < IOU_T) noobj_acc += hcf[pb] * hcf[pb];
        }

        // ---- Scalar losses (one lane per cell).
        float coord_acc = 0.0f, obj_acc = 0.0f;
        if (sub == 0) {
            #pragma unroll
            for (int tb = 0; tb < 3; tb++) {
                int pb = idx_t[tb];
                float ho = (ycf[tb] > 0.0f) ? 1.0f : 0.0f;
                float aw_p = (pb == 0) ? aw[0] : (pb == 1) ? aw[1] : aw[2];
                float ah_p = (pb == 0) ? ah[0] : (pb == 1) ? ah[1] : ah[2];
                float dx = (hcx[pb] - ycx[tb]) * (float)SD;
                float dy = (hcy[pb] - ycy[tb]) * (float)SD;
                float dlw = __logf(hw[pb] / aw_p + EPSF) - __logf(yw[tb] / aw[tb] + EPSF);
                float dlh = __logf(hh[pb] / ah_p + EPSF) - __logf(yh[tb] / ah[tb] + EPSF);
                float c = dx * dx + dy * dy + dlw * dlw + dlh * dlh;
                coord_acc += c * ho * (2.0f - yw[tb] * yh[tb]);   // SCALE_COORD
                float dc = hcf[pb] - ycf[tb];
                obj_acc += dc * dc * ho;
            }
        }

        // ---- Class loss: stream from global (argmax-dependent addresses).
        float cls_acc = 0.0f;
        #pragma unroll
        for (int tb = 0; tb < 3; tb++) {
            int pb = idx_t[tb];
            float ho = (ycf[tb] > 0.0f) ? 1.0f : 0.0f;
            const float* Hc = Hb + pb * 85 + 5;
            const float* Yc = Yb + tb * 85 + 5;
            float s = 0.0f;
            #pragma unroll
            for (int c = sub; c < 80; c += 8) {
                float d = __ldg(Hc + c) - __ldg(Yc + c);
                s += d * d;
            }
            cls_acc += s * ho;
        }

        // ---- Warp reduction (4 cells share image n) + atomics.
        coord_acc = warp_sum(coord_acc);
        cls_acc   = warp_sum(cls_acc);
        noobj_acc = warp_sum(noobj_acc);
        obj_acc   = warp_sum(obj_acc);

        if (lane == 0) {
            // layout: coord[0:64) class[64:128) noobj[128:192) obj[192:256)
            atomicAdd(out + 0 * NB + n, coord_acc);
            atomicAdd(out + 1 * NB + n, cls_acc);
            atomicAdd(out + 2 * NB + n, noobj_acc);
            atomicAdd(out + 3 * NB + n, obj_acc);
        }
    }
}

extern "C" void kernel_launch(void* const* d_in, const int* in_sizes, int n_in,
                              void* d_out, int out_size) {
    const float* yhat    = (const float*)d_in[0];
    const float* y       = (const float*)d_in[1];
    const float* anchors = (const float*)d_in[2];
    float* out = (float*)d_out;

    cudaMemsetAsync(out, 0, (size_t)out_size * sizeof(float));
    yolo_loss_kernel<<<GRIDP, 128>>>(yhat, y, anchors, out);
}

// round 14
// speedup vs baseline: 1.1380x; 1.1380x over previous
#include <cuda_runtime.h>

// Problem constants (fixed by setup_inputs)
#define NB        64
#define SD        52
#define CELLS     (SD * SD)             // 2704
#define CH        255
#define QCELLS    4                     // cells per warp
#define NQUADS    (NB * CELLS / QCELLS) // 43264
#define QPI       (CELLS / QCELLS)      // 676 quads per image
#define EPSF      1e-6f
#define IOU_T     0.7f
#define SCALE_IDX 2

__device__ __forceinline__ float warp_sum(float v) {
    #pragma unroll
    for (int o = 16; o > 0; o >>= 1) v += __shfl_down_sync(0xffffffffu, v, o);
    return v;
}

#define SEL3(i, a, b, c) ((i) == 0 ? (a) : ((i) == 1 ? (b) : (c)))

__global__ __launch_bounds__(128, 8) void yolo_loss_kernel(
    const float* __restrict__ yhat,
    const float* __restrict__ ytru,
    const float* __restrict__ anchors,
    float* __restrict__ out)
{
    const int wl   = threadIdx.x >> 5;
    const int lane = threadIdx.x & 31;
    const int quad = blockIdx.x * 4 + wl;     // 0..43263 (grid exact)
    const int n    = quad / QPI;              // image
    const int c0   = (quad % QPI) * QCELLS;

    const int g   = lane >> 3;                // cell within quad (0..3)
    const int sub = lane & 7;                 // lane within cell group
    const int cellIdx = c0 + g;
    const int gi = cellIdx / SD;
    const int gj = cellIdx % SD;

    const size_t base = ((size_t)n * CELLS + cellIdx) * CH;
    const float* Hb = yhat + base;
    const float* Yb = ytru + base;

    // ---- Box fields: broadcast LDGs per 8-lane group (R6 pattern).
    const float invS = 1.0f / (float)SD;
    const float fj = (float)gj, fi = (float)gi;

    float hcx[3], hcy[3], hw[3], hh[3], hcf[3];
    float ycx[3], ycy[3], yw[3], yh[3], ycf[3];
    #pragma unroll
    for (int b = 0; b < 3; b++) {
        const float* hb = Hb + b * 85;
        const float* yb = Yb + b * 85;
        hcx[b] = (__ldg(hb + 0) + fj) * invS;
        hcy[b] = (__ldg(hb + 1) + fi) * invS;
        hw[b]  =  __ldg(hb + 2);
        hh[b]  =  __ldg(hb + 3);
        hcf[b] =  __ldg(hb + 4);
        ycx[b] = (__ldg(yb + 0) + fj) * invS;
        ycy[b] = (__ldg(yb + 1) + fi) * invS;
        yw[b]  =  __ldg(yb + 2);
        yh[b]  =  __ldg(yb + 3);
        ycf[b] =  __ldg(yb + 4);
    }

    // ---- IOU 3x3: per-pb max -> noobj term; per-tb argmax -> responsible box.
    int   idx_t[3];
    float best_t[3] = {-1.0f, -1.0f, -1.0f};
    float noobj_acc = 0.0f;
    #pragma unroll
    for (int pb = 0; pb < 3; pb++) {
        float px1 = hcx[pb] - 0.5f * hw[pb], px2 = hcx[pb] + 0.5f * hw[pb];
        float py1 = hcy[pb] - 0.5f * hh[pb], py2 = hcy[pb] + 0.5f * hh[pb];
        float pa  = hw[pb] * hh[pb];
        float m = -1.0f;
        #pragma unroll
        for (int tb = 0; tb < 3; tb++) {
            float wi = fmaxf(fminf(px2, ycx[tb] + 0.5f * yw[tb]) -
                             fmaxf(px1, ycx[tb] - 0.5f * yw[tb]), 0.0f);
            float hi = fmaxf(fminf(py2, ycy[tb] + 0.5f * yh[tb]) -
                             fmaxf(py1, ycy[tb] - 0.5f * yh[tb]), 0.0f);
            float inter = wi * hi;
            float uni = pa + yw[tb] * yh[tb] - inter;
            float iou = inter / (uni + EPSF);
            m = fmaxf(m, iou);
            if (iou > best_t[tb]) { best_t[tb] = iou; idx_t[tb] = pb; }
        }
        if (sub == 0 && m < IOU_T) noobj_acc += hcf[pb] * hcf[pb];  // NO_OBJ_V3
    }

    const float ho0 = (ycf[0] > 0.0f) ? 1.0f : 0.0f;
    const float ho1 = (ycf[1] > 0.0f) ? 1.0f : 0.0f;
    const float ho2 = (ycf[2] > 0.0f) ? 1.0f : 0.0f;

    // ---- Scalar losses (one lane per cell).
    float coord_acc = 0.0f, obj_acc = 0.0f;
    if (sub == 0) {
        const float* anc = anchors + SCALE_IDX * 6;
        #pragma unroll
        for (int tb = 0; tb < 3; tb++) {
            int pb = idx_t[tb];
            float ho = (tb == 0) ? ho0 : (tb == 1) ? ho1 : ho2;
            float aw_p = __ldg(anc + pb * 2), ah_p = __ldg(anc + pb * 2 + 1);
            float aw_t = __ldg(anc + tb * 2), ah_t = __ldg(anc + tb * 2 + 1);
            float dx = (hcx[pb] - ycx[tb]) * (float)SD;   // == x_hat - x_true
            float dy = (hcy[pb] - ycy[tb]) * (float)SD;
            float dlw = __logf(hw[pb] / aw_p + EPSF) - __logf(yw[tb] / aw_t + EPSF);
            float dlh = __logf(hh[pb] / ah_p + EPSF) - __logf(yh[tb] / ah_t + EPSF);
            float c = dx * dx + dy * dy + dlw * dlw + dlh * dlh;
            coord_acc += c * ho * (2.0f - yw[tb] * yh[tb]);   // SCALE_COORD
            float dc = hcf[pb] - ycf[tb];
            obj_acc += dc * dc * ho;
        }
    }

    // ---- Class loss: load ALL SIX windows per chunk (addresses independent
    // of the argmax -> every load can issue before/through the IOU phase);
    // resolve the responsible-box permutation with register selects.
    const int p0 = idx_t[0], p1 = idx_t[1], p2 = idx_t[2];
    float cls_acc = 0.0f;
    #pragma unroll
    for (int k = 0; k < 10; k++) {
        int c = 5 + sub + 8 * k;              // covers channels 5..84 exactly
        float a0 = __ldg(Hb +   0 + c);
        float a1 = __ldg(Hb +  85 + c);
        float a2 = __ldg(Hb + 170 + c);
        float b0 = __ldg(Yb +   0 + c);
        float b1 = __ldg(Yb +  85 + c);
        float b2 = __ldg(Yb + 170 + c);
        float s0 = SEL3(p0, a0, a1, a2) - b0;
        float s1 = SEL3(p1, a0, a1, a2) - b1;
        float s2 = SEL3(p2, a0, a1, a2) - b2;
        cls_acc += s0 * s0 * ho0 + s1 * s1 * ho1 + s2 * s2 * ho2;
    }

    // ---- Warp reduction (all 4 cells share image n) + atomics.
    coord_acc = warp_sum(coord_acc);
    cls_acc   = warp_sum(cls_acc);
    noobj_acc = warp_sum(noobj_acc);
    obj_acc   = warp_sum(obj_acc);

    if (lane == 0) {
        // layout: coord[0:64) class[64:128) noobj[128:192) obj[192:256) prior
        atomicAdd(out + 0 * NB + n, coord_acc);
        atomicAdd(out + 1 * NB + n, cls_acc);
        atomicAdd(out + 2 * NB + n, noobj_acc);
        atomicAdd(out + 3 * NB + n, obj_acc);
    }
}

extern "C" void kernel_launch(void* const* d_in, const int* in_sizes, int n_in,
                              void* d_out, int out_size) {
    const float* yhat    = (const float*)d_in[0];
    const float* y       = (const float*)d_in[1];
    const float* anchors = (const float*)d_in[2];
    float* out = (float*)d_out;

    cudaMemsetAsync(out, 0, (size_t)out_size * sizeof(float));
    yolo_loss_kernel<<<NQUADS / 4, 128>>>(yhat, y, anchors, out);  // 10816 blocks
}